// round 10
// baseline (speedup 1.0000x reference)
#include <cuda_runtime.h>

// NSLayer: out = X + (w0 A + ... + w6 A^7 + w7 I) X,  A = I - X X^T
// 262144 independent 8x8 fp32 matrices, ONE thread per matrix.
// R8 = R7 algebra (B = A^2 even/odd split: V=BX,W=BV,Z=BW;
//   t = w0X+w2V+w4W+w6Z; u=(1+w7)X+w1V+w3W+w5Z; out = u + A t)
// + occupancy push: A evicted to smem after B-phase (read back only in the
// final matvec), cp-chain loop kept dynamic -> regs <=170 -> 3 CTAs (12
// warps/SM) instead of 2 (8 warps). fma2/thread = 1712, rt3 floor ~35us.

static constexpr int MPB = 128;   // matrices per block == threads per block
static constexpr int MS  = 68;    // padded staging stride in floats

typedef unsigned long long u64;

static constexpr int SMEM_A_BYTES = 36 * MPB * 8;        // 36864
static constexpr int SMEM_S_BYTES = MPB * MS * 4;        // 34816
static constexpr int SMEM_TOTAL   = SMEM_A_BYTES + SMEM_S_BYTES;  // 71680

__device__ __forceinline__ u64 pack2(float lo, float hi) {
    u64 r; asm("mov.b64 %0, {%1, %2};" : "=l"(r) : "f"(lo), "f"(hi)); return r;
}
__device__ __forceinline__ float hadd2(u64 v) {
    float lo, hi; asm("mov.b64 {%0, %1}, %2;" : "=f"(lo), "=f"(hi) : "l"(v));
    return lo + hi;
}
__device__ __forceinline__ u64 fma2(u64 a, u64 b, u64 c) {
    u64 d; asm("fma.rn.f32x2 %0, %1, %2, %3;" : "=l"(d) : "l"(a), "l"(b), "l"(c)); return d;
}
__device__ __forceinline__ u64 mul2(u64 a, u64 b) {
    u64 d; asm("mul.rn.f32x2 %0, %1, %2;" : "=l"(d) : "l"(a), "l"(b)); return d;
}

#define TRI(r, k) ((r) >= (k) ? ((r) * ((r) + 1) / 2 + (k)) : ((k) * ((k) + 1) / 2 + (r)))

__global__ __launch_bounds__(128, 3)
void nslayer_kernel(const float* __restrict__ x,
                    const float* __restrict__ weight,
                    float* __restrict__ out)
{
    extern __shared__ __align__(16) unsigned char dynsm[];
    u64*   sA = reinterpret_cast<u64*>(dynsm);                   // per-thread A slab
    float* s  = reinterpret_cast<float*>(dynsm + SMEM_A_BYTES);  // staging

    const int tid = threadIdx.x;
    const size_t base = (size_t)blockIdx.x * (MPB * 64);

    // ---- preload weights, pre-broadcast ----
    const float4 wA4 = __ldg(reinterpret_cast<const float4*>(weight));
    const float4 wB4 = __ldg(reinterpret_cast<const float4*>(weight) + 1);
    const u64 w0_2 = pack2(wA4.x, wA4.x);
    const u64 w1_2 = pack2(wA4.y, wA4.y);
    const u64 w2_2 = pack2(wA4.z, wA4.z);
    const u64 w3_2 = pack2(wA4.w, wA4.w);
    const u64 w4_2 = pack2(wB4.x, wB4.x);
    const u64 w5_2 = pack2(wB4.y, wB4.y);
    const u64 w6_2 = pack2(wB4.z, wB4.z);
    const float w7p1 = wB4.w + 1.0f;
    const u64 w7p1_2 = pack2(w7p1, w7p1);

    // ---- coalesced load: block's 32KB chunk -> padded staging smem ----
    const float4* gin = reinterpret_cast<const float4*>(x + base);
#pragma unroll
    for (int k = 0; k < 16; k++) {
        int l4 = tid + k * 128;
        float4 v = gin[l4];
        int l = l4 << 2, m = l >> 6, w = l & 63;
        *reinterpret_cast<float4*>(&s[m * MS + w]) = v;
    }
    __syncthreads();

    // ---- A = I - X X^T : triangle via packed row dots -> broadcast form;
    //      each entry also stored to my smem slab (read back in final mv) ----
    u64 A2b[36];
    {
        u64 X2[8][4];
#pragma unroll
        for (int r = 0; r < 8; r++) {
            ulonglong2 p0 = *reinterpret_cast<const ulonglong2*>(&s[tid * MS + r * 8]);
            ulonglong2 p1 = *reinterpret_cast<const ulonglong2*>(&s[tid * MS + r * 8 + 4]);
            X2[r][0] = p0.x; X2[r][1] = p0.y; X2[r][2] = p1.x; X2[r][3] = p1.y;
        }
#pragma unroll
        for (int r = 0; r < 8; r++)
#pragma unroll
            for (int c = 0; c <= r; c++) {
                u64 d2 = mul2(X2[r][0], X2[c][0]);
#pragma unroll
                for (int kp = 1; kp < 4; kp++) d2 = fma2(X2[r][kp], X2[c][kp], d2);
                float v = ((r == c) ? 1.0f : 0.0f) - hadd2(d2);
                u64 v2 = pack2(v, v);
                A2b[TRI(r, c)] = v2;
                sA[TRI(r, c) * MPB + tid] = v2;
            }
    }   // X2 dies here

    // ---- B = A*A triangle, broadcast x broadcast (result already packed) ----
    u64 B2b[36];
#pragma unroll
    for (int r = 0; r < 8; r++)
#pragma unroll
        for (int c = 0; c <= r; c++) {
            u64 d2 = mul2(A2b[TRI(r, 0)], A2b[TRI(0, c)]);
#pragma unroll
            for (int k = 1; k < 8; k++)
                d2 = fma2(A2b[TRI(r, k)], A2b[TRI(k, c)], d2);
            B2b[TRI(r, c)] = d2;
        }
    // A2b registers die here; final matvec reads A from sA.

    // ---- per column-pair chain (DYNAMIC loop: one chain's regs live) ----
#pragma unroll 1
    for (int cp = 0; cp < 4; cp++) {
        u64 xv[8], t[8], u[8], v[8];
#pragma unroll
        for (int k = 0; k < 8; k++)
            xv[k] = *reinterpret_cast<const u64*>(&s[tid * MS + k * 8 + 2 * cp]);

        // v = B x ; t = w0 x + w2 v ; u = (1+w7) x + w1 v
#pragma unroll
        for (int r = 0; r < 8; r++) {
            u64 d2 = mul2(B2b[TRI(r, 0)], xv[0]);
#pragma unroll
            for (int k = 1; k < 8; k++) d2 = fma2(B2b[TRI(r, k)], xv[k], d2);
            v[r] = d2;
        }
#pragma unroll
        for (int r = 0; r < 8; r++) {
            t[r] = fma2(w2_2, v[r], mul2(w0_2, xv[r]));
            u[r] = fma2(w1_2, v[r], mul2(w7p1_2, xv[r]));
        }
        // w = B v ; t += w4 w ; u += w3 w   (xv dead, reuse as w)
#pragma unroll
        for (int r = 0; r < 8; r++) {
            u64 d2 = mul2(B2b[TRI(r, 0)], v[0]);
#pragma unroll
            for (int k = 1; k < 8; k++) d2 = fma2(B2b[TRI(r, k)], v[k], d2);
            xv[r] = d2;
        }
#pragma unroll
        for (int r = 0; r < 8; r++) {
            t[r] = fma2(w4_2, xv[r], t[r]);
            u[r] = fma2(w3_2, xv[r], u[r]);
        }
        // z = B w ; t += w6 z ; u += w5 z   (v dead, reuse as z)
#pragma unroll
        for (int r = 0; r < 8; r++) {
            u64 d2 = mul2(B2b[TRI(r, 0)], xv[0]);
#pragma unroll
            for (int k = 1; k < 8; k++) d2 = fma2(B2b[TRI(r, k)], xv[k], d2);
            v[r] = d2;
        }
#pragma unroll
        for (int r = 0; r < 8; r++) {
            t[r] = fma2(w6_2, v[r], t[r]);
            u[r] = fma2(w5_2, v[r], u[r]);
        }

        // o = u + A t  (A read back from smem slab), store this column pair
#pragma unroll
        for (int r = 0; r < 8; r++) {
            u64 d2 = u[r];
#pragma unroll
            for (int k = 0; k < 8; k++)
                d2 = fma2(sA[TRI(r, k) * MPB + tid], t[k], d2);
            *reinterpret_cast<u64*>(&s[tid * MS + r * 8 + 2 * cp]) = d2;
        }
    }
    __syncthreads();

    // ---- coalesced store: padded staging smem -> output chunk ----
    float4* gout = reinterpret_cast<float4*>(out + base);
#pragma unroll
    for (int k = 0; k < 16; k++) {
        int l4 = tid + k * 128;
        int l = l4 << 2, m = l >> 6, w = l & 63;
        gout[l4] = *reinterpret_cast<const float4*>(&s[m * MS + w]);
    }
}

extern "C" void kernel_launch(void* const* d_in, const int* in_sizes, int n_in,
                              void* d_out, int out_size) {
    const float* x = (const float*)d_in[0];
    const float* w = (const float*)d_in[1];
    float* out = (float*)d_out;
    // idempotent, deterministic, allocation-free host call (capture-safe)
    cudaFuncSetAttribute(nslayer_kernel,
                         cudaFuncAttributeMaxDynamicSharedMemorySize, SMEM_TOTAL);
    int nmat = in_sizes[0] / 64;          // 262144
    int blocks = nmat / MPB;              // 2048 (exact)
    nslayer_kernel<<<blocks, MPB, SMEM_TOTAL>>>(x, w, out);
}

// round 11
// speedup vs baseline: 1.1585x; 1.1585x over previous
#include <cuda_runtime.h>
#include <cstdint>

// NSLayer: out = X + (w0 A + ... + w6 A^7 + w7 I) X,  A = I - X X^T
// 262144 independent 8x8 fp32 matrices, ONE thread per matrix.
// R9 = persistent CTAs (2/SM) + TMA bulk double-buffered input prefetch
//      + R7 algebra (B=A^2 even/odd split) with packed-dot B build.
// All heavy math in packed fma.rn.f32x2 (FFMA2, rt~2).

typedef unsigned long long u64;

static constexpr int TPB = 128;           // threads = matrices per chunk
static constexpr int GRID = 304;          // 2 CTAs per SM on 152 SMs
static constexpr int NCHUNK = 2048;       // 262144 / 128
static constexpr int CHUNK_FLOATS = 8192; // 128 matrices * 64
static constexpr int CHUNK_BYTES = 32768;
static constexpr int MS = 68;             // padded matrix stride (floats)
static constexpr int PAD_BYTES = TPB * MS * 4;            // 34816
static constexpr int SMEM_TOTAL = 2 * CHUNK_BYTES + PAD_BYTES + 16;

__device__ __forceinline__ uint32_t smem_u32(const void* p) {
    uint32_t a;
    asm("{ .reg .u64 t; cvta.to.shared.u64 t, %1; cvt.u32.u64 %0, t; }"
        : "=r"(a) : "l"(p));
    return a;
}
__device__ __forceinline__ u64 pack2(float lo, float hi) {
    u64 r; asm("mov.b64 %0, {%1, %2};" : "=l"(r) : "f"(lo), "f"(hi)); return r;
}
__device__ __forceinline__ float hadd2(u64 v) {
    float lo, hi; asm("mov.b64 {%0, %1}, %2;" : "=f"(lo), "=f"(hi) : "l"(v));
    return lo + hi;
}
__device__ __forceinline__ u64 fma2(u64 a, u64 b, u64 c) {
    u64 d; asm("fma.rn.f32x2 %0, %1, %2, %3;" : "=l"(d) : "l"(a), "l"(b), "l"(c)); return d;
}
__device__ __forceinline__ u64 mul2(u64 a, u64 b) {
    u64 d; asm("mul.rn.f32x2 %0, %1, %2;" : "=l"(d) : "l"(a), "l"(b)); return d;
}
__device__ __forceinline__ void mbar_init(uint32_t mbar, uint32_t cnt) {
    asm volatile("mbarrier.init.shared.b64 [%0], %1;" :: "r"(mbar), "r"(cnt) : "memory");
}
__device__ __forceinline__ void mbar_expect_tx(uint32_t mbar, uint32_t bytes) {
    asm volatile("mbarrier.arrive.expect_tx.shared.b64 _, [%0], %1;"
                 :: "r"(mbar), "r"(bytes) : "memory");
}
__device__ __forceinline__ void mbar_wait(uint32_t mbar, uint32_t parity) {
    uint32_t done;
    asm volatile(
        "{\n\t.reg .pred p;\n\t"
        "mbarrier.try_wait.parity.acquire.cta.shared::cta.b64 p, [%1], %2;\n\t"
        "selp.b32 %0, 1, 0, p;\n\t}"
        : "=r"(done) : "r"(mbar), "r"(parity) : "memory");
    if (!done) {
        asm volatile(
            "{\n\t.reg .pred P1;\n\t"
            "WL_%=:\n\t"
            "mbarrier.try_wait.parity.acquire.cta.shared::cta.b64 P1, [%0], %1, 0x989680;\n\t"
            "@P1 bra.uni WD_%=;\n\t"
            "bra.uni WL_%=;\n\t"
            "WD_%=:\n\t}"
            :: "r"(mbar), "r"(parity) : "memory");
    }
}
__device__ __forceinline__ void bulk_load(uint32_t smem_dst, const void* gsrc, uint32_t mbar) {
    asm volatile(
        "cp.async.bulk.shared::cta.global.mbarrier::complete_tx::bytes [%0], [%1], %2, [%3];"
        :: "r"(smem_dst), "l"(gsrc), "r"((uint32_t)CHUNK_BYTES), "r"(mbar) : "memory");
}

#define TRI(r, k) ((r) >= (k) ? ((r) * ((r) + 1) / 2 + (k)) : ((k) * ((k) + 1) / 2 + (r)))

__global__ __launch_bounds__(TPB, 2)
void nslayer_kernel(const float* __restrict__ x,
                    const float* __restrict__ weight,
                    float* __restrict__ out)
{
    extern __shared__ __align__(128) unsigned char sm[];
    float* lin = reinterpret_cast<float*>(sm);                      // 2 linear bufs
    float* pad = reinterpret_cast<float*>(sm + 2 * CHUNK_BYTES);    // padded work area
    const uint32_t smbase = smem_u32(sm);
    const uint32_t mb = smbase + 2 * CHUNK_BYTES + PAD_BYTES;       // 2 mbarriers

    const int tid = threadIdx.x;
    const int bid = blockIdx.x;
    const int W = (NCHUNK - 1 - bid) / GRID + 1;   // chunks for this CTA (6 or 7)

    // ---- weights, pre-broadcast ----
    const float4 wA4 = __ldg(reinterpret_cast<const float4*>(weight));
    const float4 wB4 = __ldg(reinterpret_cast<const float4*>(weight) + 1);
    const u64 w0_2 = pack2(wA4.x, wA4.x);
    const u64 w1_2 = pack2(wA4.y, wA4.y);
    const u64 w2_2 = pack2(wA4.z, wA4.z);
    const u64 w3_2 = pack2(wA4.w, wA4.w);
    const u64 w4_2 = pack2(wB4.x, wB4.x);
    const u64 w5_2 = pack2(wB4.y, wB4.y);
    const u64 w6_2 = pack2(wB4.z, wB4.z);
    const float w7p1 = wB4.w + 1.0f;
    const u64 w7p1_2 = pack2(w7p1, w7p1);

    if (tid == 0) { mbar_init(mb, 1); mbar_init(mb + 8, 1); }
    __syncthreads();
    if (tid == 0) {
#pragma unroll
        for (int p = 0; p < 2; p++)
            if (p < W) {
                mbar_expect_tx(mb + 8 * p, CHUNK_BYTES);
                bulk_load(smbase + p * CHUNK_BYTES,
                          x + (size_t)(bid + p * GRID) * CHUNK_FLOATS, mb + 8 * p);
            }
    }

    for (int wi = 0; wi < W; wi++) {
        const int b = wi & 1;
        mbar_wait(mb + 8 * b, (wi >> 1) & 1);

        // ---- copy-in: linear TMA buf -> padded (conflict-free both sides) ----
        const float4* src = reinterpret_cast<const float4*>(lin + b * CHUNK_FLOATS);
#pragma unroll
        for (int k = 0; k < 16; k++) {
            int l4 = tid + k * TPB;
            float4 v = src[l4];
            int l = l4 << 2, m = l >> 6, o = l & 63;
            *reinterpret_cast<float4*>(&pad[m * MS + o]) = v;
        }
        __syncthreads();

        // buffer b is now free: prefetch chunk wi+2 into it
        if (tid == 0 && wi + 2 < W) {
            mbar_expect_tx(mb + 8 * b, CHUNK_BYTES);
            bulk_load(smbase + b * CHUNK_BYTES,
                      x + (size_t)(bid + (size_t)(wi + 2) * GRID) * CHUNK_FLOATS,
                      mb + 8 * b);
        }

        // ================= compute: matrix tid of this chunk =================
        // Gram: A = I - X X^T (scalar triangle Cs)
        float Cs[36];
        {
            u64 X2[8][4];
#pragma unroll
            for (int r = 0; r < 8; r++) {
                ulonglong2 p0 = *reinterpret_cast<const ulonglong2*>(&pad[tid * MS + r * 8]);
                ulonglong2 p1 = *reinterpret_cast<const ulonglong2*>(&pad[tid * MS + r * 8 + 4]);
                X2[r][0] = p0.x; X2[r][1] = p0.y; X2[r][2] = p1.x; X2[r][3] = p1.y;
            }
#pragma unroll
            for (int r = 0; r < 8; r++)
#pragma unroll
                for (int c = 0; c <= r; c++) {
                    u64 d2 = mul2(X2[r][0], X2[c][0]);
#pragma unroll
                    for (int kp = 1; kp < 4; kp++) d2 = fma2(X2[r][kp], X2[c][kp], d2);
                    Cs[TRI(r, c)] = ((r == c) ? 1.0f : 0.0f) - hadd2(d2);
                }
        }
        // A in pair-row layout for packed-dot B build
        u64 B2b[36];
        {
            u64 A2p[8][4];
#pragma unroll
            for (int r = 0; r < 8; r++)
#pragma unroll
                for (int kp = 0; kp < 4; kp++)
                    A2p[r][kp] = pack2(Cs[TRI(r, 2 * kp)], Cs[TRI(r, 2 * kp + 1)]);
            // B = A*A: A symmetric -> B[r][c] = <A row r, A row c> (packed dots)
#pragma unroll
            for (int r = 0; r < 8; r++)
#pragma unroll
                for (int c = 0; c <= r; c++) {
                    u64 d2 = mul2(A2p[r][0], A2p[c][0]);
#pragma unroll
                    for (int kp = 1; kp < 4; kp++) d2 = fma2(A2p[r][kp], A2p[c][kp], d2);
                    float v = hadd2(d2);
                    B2b[TRI(r, c)] = pack2(v, v);
                }
        }
        // A broadcast form for the final matvec
        u64 A2b[36];
#pragma unroll
        for (int e = 0; e < 36; e++) A2b[e] = pack2(Cs[e], Cs[e]);

        // per column-pair: V=BX, W=BV, Z=BW; t,u folds; out = u + A t
#pragma unroll
        for (int cp = 0; cp < 4; cp++) {
            u64 xv[8], t[8], u[8], v[8];
#pragma unroll
            for (int k = 0; k < 8; k++)
                xv[k] = *reinterpret_cast<const u64*>(&pad[tid * MS + k * 8 + 2 * cp]);
            // v = B x
#pragma unroll
            for (int r = 0; r < 8; r++) {
                u64 d2 = mul2(B2b[TRI(r, 0)], xv[0]);
#pragma unroll
                for (int k = 1; k < 8; k++) d2 = fma2(B2b[TRI(r, k)], xv[k], d2);
                v[r] = d2;
            }
#pragma unroll
            for (int r = 0; r < 8; r++) {
                t[r] = fma2(w2_2, v[r], mul2(w0_2, xv[r]));
                u[r] = fma2(w1_2, v[r], mul2(w7p1_2, xv[r]));
            }
            // w = B v (into xv)
#pragma unroll
            for (int r = 0; r < 8; r++) {
                u64 d2 = mul2(B2b[TRI(r, 0)], v[0]);
#pragma unroll
                for (int k = 1; k < 8; k++) d2 = fma2(B2b[TRI(r, k)], v[k], d2);
                xv[r] = d2;
            }
#pragma unroll
            for (int r = 0; r < 8; r++) {
                t[r] = fma2(w4_2, xv[r], t[r]);
                u[r] = fma2(w3_2, xv[r], u[r]);
            }
            // z = B w (into v)
#pragma unroll
            for (int r = 0; r < 8; r++) {
                u64 d2 = mul2(B2b[TRI(r, 0)], xv[0]);
#pragma unroll
                for (int k = 1; k < 8; k++) d2 = fma2(B2b[TRI(r, k)], xv[k], d2);
                v[r] = d2;
            }
#pragma unroll
            for (int r = 0; r < 8; r++) {
                t[r] = fma2(w6_2, v[r], t[r]);
                u[r] = fma2(w5_2, v[r], u[r]);
            }
            // o = u + A t, store into my pad region (cp columns now dead)
#pragma unroll
            for (int r = 0; r < 8; r++) {
                u64 d2 = u[r];
#pragma unroll
                for (int k = 0; k < 8; k++) d2 = fma2(A2b[TRI(r, k)], t[k], d2);
                *reinterpret_cast<u64*>(&pad[tid * MS + r * 8 + 2 * cp]) = d2;
            }
        }
        __syncthreads();

        // ---- coalesced store: padded -> global ----
        float4* gout = reinterpret_cast<float4*>(out + (size_t)(bid + (size_t)wi * GRID) * CHUNK_FLOATS);
#pragma unroll
        for (int k = 0; k < 16; k++) {
            int l4 = tid + k * TPB;
            int l = l4 << 2, m = l >> 6, o = l & 63;
            gout[l4] = *reinterpret_cast<const float4*>(&pad[m * MS + o]);
        }
        __syncthreads();   // protect pad before next iteration's copy-in
    }
}

extern "C" void kernel_launch(void* const* d_in, const int* in_sizes, int n_in,
                              void* d_out, int out_size) {
    const float* x = (const float*)d_in[0];
    const float* w = (const float*)d_in[1];
    float* out = (float*)d_out;
    cudaFuncSetAttribute(nslayer_kernel,
                         cudaFuncAttributeMaxDynamicSharedMemorySize, SMEM_TOTAL);
    nslayer_kernel<<<GRID, TPB, SMEM_TOTAL>>>(x, w, out);
}